// round 13
// baseline (speedup 1.0000x reference)
#include <cuda_runtime.h>
#include <cuda_fp16.h>
#include <cstdint>

#define TOKENS   32768
#define NTHREADS 1024
#define CONS_T   768          // 24 consumer warps; 8 producer warps
#define PROD_T   256
#define GRID     152

#define TOK_A    32           // 96 rows exact
#define TILES_A2 1024         // 32768/32
#define TOK_B    10           // 90 rows (+6 pad)
#define TILES_B2 3277         // ceil(32768/10)

#define OFF_W    0            // 256 rows x 512B = 131072
#define BUF_SZ   49152        // 96 rows x 512B
#define OFF_B0   131072
#define OFF_B1   (131072 + BUF_SZ)
#define SMEM_BYTES (131072 + 2 * BUF_SZ)   // 229376 <= 227KB opt-in

#define BAR_FULL(b)  (1 + (b))
#define BAR_EMPTY(b) (3 + (b))

__device__ __half g_XL[(size_t)TOKENS * 3 * 256];
__device__ __half g_XR[(size_t)TOKENS * 3 * 256];

__device__ __forceinline__ uint32_t smem_u32(const void* p) {
    uint32_t a;
    asm("{ .reg .u64 t; cvta.to.shared.u64 t, %1; cvt.u32.u64 %0, t; }" : "=r"(a) : "l"(p));
    return a;
}
__device__ __forceinline__ void bar_sync(int id, int cnt) {
    asm volatile("bar.sync %0, %1;" :: "r"(id), "r"(cnt) : "memory");
}
__device__ __forceinline__ void bar_arrive(int id, int cnt) {
    asm volatile("bar.arrive %0, %1;" :: "r"(id), "r"(cnt) : "memory");
}
// XOR swizzle: row stride 512B, 16B chunk index ^ (row&7)
__device__ __forceinline__ uint32_t sw(uint32_t row, uint32_t kc) {
    return row * 512u + (((kc ^ (row & 7u)) & 31u) << 4);
}
__device__ __forceinline__ void ldsm_x4(uint32_t addr, uint32_t* r) {
    asm volatile("ldmatrix.sync.aligned.m8n8.x4.shared.b16 {%0,%1,%2,%3}, [%4];"
                 : "=r"(r[0]), "=r"(r[1]), "=r"(r[2]), "=r"(r[3]) : "r"(addr));
}
__device__ __forceinline__ void mma16816(float* c, const uint32_t* a, const uint32_t* b) {
    asm volatile("mma.sync.aligned.m16n8k16.row.col.f32.f16.f16.f32 "
                 "{%0,%1,%2,%3}, {%4,%5,%6,%7}, {%8,%9}, {%0,%1,%2,%3};"
                 : "+f"(c[0]), "+f"(c[1]), "+f"(c[2]), "+f"(c[3])
                 : "r"(a[0]), "r"(a[1]), "r"(a[2]), "r"(a[3]), "r"(b[0]), "r"(b[1]));
}
__device__ __forceinline__ uint32_t f2h2(float a, float b) {
    __half2 h = __floats2half2_rn(a, b);
    return *reinterpret_cast<uint32_t*>(&h);
}
__device__ __forceinline__ uint32_t hmul2u(uint32_t a, uint32_t b) {
    __half2 r = __hmul2(*reinterpret_cast<__half2*>(&a), *reinterpret_cast<__half2*>(&b));
    return *reinterpret_cast<uint32_t*>(&r);
}

// Full 256-row fp32 weight -> fp16 swizzled smem (128KB), all 1024 threads
__device__ __forceinline__ void load_w(char* smem, const float* W, int tid) {
    for (int c = tid; c < 8192; c += NTHREADS) {
        int row = c >> 5, kc = c & 31;
        const float* s = W + (size_t)row * 256 + kc * 8;
        float4 f0 = *reinterpret_cast<const float4*>(s);
        float4 f1 = *reinterpret_cast<const float4*>(s + 4);
        uint4 v;
        v.x = f2h2(f0.x, f0.y); v.y = f2h2(f0.z, f0.w);
        v.z = f2h2(f1.x, f1.y); v.w = f2h2(f1.z, f1.w);
        *reinterpret_cast<uint4*>(smem + OFF_W + sw(row, kc)) = v;
    }
}

// GEMM: acc[M rows from a_base @ r0][N cols from b_base @ n0], K=256.
// 24 warps; fragments via ldsm from [row][k] 512B-pitch swizzled tiles.
__device__ __forceinline__ void gemm_tile(uint32_t sb, uint32_t a_base, uint32_t b_base,
                                          int lane, int r0, int n0, float acc[2][4][4]) {
    #pragma unroll
    for (int mt = 0; mt < 2; mt++)
        #pragma unroll
        for (int nt = 0; nt < 4; nt++)
            #pragma unroll
            for (int q = 0; q < 4; q++) acc[mt][nt][q] = 0.f;

    const int la_row = (lane & 7) | (((lane >> 3) & 1) << 3);
    const int la_kc  = lane >> 4;
    const int lb_row = (lane & 7) | ((lane >> 4) << 3);
    const int lb_kc  = (lane >> 3) & 1;

    #pragma unroll 4
    for (int kc = 0; kc < 32; kc += 2) {
        uint32_t a[2][4], b[2][4];
        #pragma unroll
        for (int mt = 0; mt < 2; mt++)
            ldsm_x4(sb + a_base + sw(r0 + mt * 16 + la_row, kc + la_kc), a[mt]);
        #pragma unroll
        for (int p = 0; p < 2; p++)
            ldsm_x4(sb + b_base + sw(n0 + p * 16 + lb_row, kc + lb_kc), b[p]);
        #pragma unroll
        for (int mt = 0; mt < 2; mt++)
            #pragma unroll
            for (int nt = 0; nt < 4; nt++)
                mma16816(acc[mt][nt], a[mt], &b[nt >> 1][(nt & 1) * 2]);
    }
}

// ---- kA (merged L/R): XO[(t*3+i), r] = sum_I x[t,I,i] * W[r,I]; 32 tokens/tile ----
__global__ void __launch_bounds__(NTHREADS, 1) kA(const float* __restrict__ x_l,
                                                  const float* __restrict__ x_r,
                                                  const float* __restrict__ w_l,
                                                  const float* __restrict__ w_r) {
    extern __shared__ __align__(128) char smem[];
    uint32_t sb = smem_u32(smem);
    const int tid = threadIdx.x, lane = tid & 31;
    const int side = blockIdx.x >= GRID;
    const int bx = side ? blockIdx.x - GRID : blockIdx.x;
    const float* x = side ? x_r : x_l;
    __half* XO = side ? g_XR : g_XL;

    load_w(smem, side ? w_r : w_l, tid);
    __syncthreads();

    if (tid < CONS_T) {                       // ---- consumers ----
        const int wid = tid >> 5;
        const int r0 = (wid >> 3) * 32, n0 = (wid & 7) * 32;
        int lt = 0;
        for (int tile = bx; tile < TILES_A2; tile += GRID, lt++) {
            int b = lt & 1;
            uint32_t boff = b ? OFF_B1 : OFF_B0;
            bar_sync(BAR_FULL(b), NTHREADS);

            float acc[2][4][4];
            gemm_tile(sb, boff, OFF_W, lane, r0, n0, acc);
            bar_arrive(BAR_EMPTY(b), NTHREADS);   // buffer free; store from regs

            int t0 = tile * TOK_A;
            #pragma unroll
            for (int mt = 0; mt < 2; mt++) {
                int row = r0 + mt * 16 + (lane >> 2);
                __half* d0 = XO + ((size_t)(t0 * 3 + row)) * 256;
                __half* d1 = XO + ((size_t)(t0 * 3 + row + 8)) * 256;
                #pragma unroll
                for (int nt = 0; nt < 4; nt++) {
                    int col = n0 + nt * 8 + (lane & 3) * 2;
                    *reinterpret_cast<uint32_t*>(d0 + col) = f2h2(acc[mt][nt][0], acc[mt][nt][1]);
                    *reinterpret_cast<uint32_t*>(d1 + col) = f2h2(acc[mt][nt][2], acc[mt][nt][3]);
                }
            }
        }
    } else {                                  // ---- producers (build only) ----
        const int ptid = tid - CONS_T;
        int lt = 0;
        for (int tile = bx; tile < TILES_A2; tile += GRID, lt++) {
            int b = lt & 1;
            uint32_t boff = b ? OFF_B1 : OFF_B0;
            if (lt >= 2) bar_sync(BAR_EMPTY(b), NTHREADS);
            const float* src = x + (size_t)(tile * TOK_A) * 768;
            for (int q = ptid; q < 4096; q += PROD_T) {
                int tl = q >> 7, I2 = (q & 127) << 1;
                const float* s = src + tl * 768 + I2 * 3;
                float v0 = s[0], v1 = s[1], v2 = s[2], v3 = s[3], v4 = s[4], v5 = s[5];
                int row = tl * 3;
                uint32_t kc = (uint32_t)I2 >> 3, off = ((uint32_t)I2 & 7u) * 2u;
                *reinterpret_cast<uint32_t*>(smem + boff + sw(row, kc) + off)     = f2h2(v0, v3);
                *reinterpret_cast<uint32_t*>(smem + boff + sw(row + 1, kc) + off) = f2h2(v1, v4);
                *reinterpret_cast<uint32_t*>(smem + boff + sw(row + 2, kc) + off) = f2h2(v2, v5);
            }
            bar_arrive(BAR_FULL(b), NTHREADS);
        }
    }
}

// ---- kB (transposed): D[O, s=(t,ij)] = sum_r Wo[O,r] * P[s,r]; 10 tokens/tile ----
__global__ void __launch_bounds__(NTHREADS, 1) kB(const float* __restrict__ Wo,
                                                  float* __restrict__ out) {
    extern __shared__ __align__(128) char smem[];
    uint32_t sb = smem_u32(smem);
    const int tid = threadIdx.x, lane = tid & 31;

    load_w(smem, Wo, tid);
    __syncthreads();

    if (tid < CONS_T) {                       // ---- consumers ----
        const int wid = tid >> 5;
        const int r0 = (wid & 7) * 32;        // O dim: 8 warps x 32
        const int n0 = (wid >> 3) * 32;       // s dim: 3 warps x 32
        int lt = 0;
        for (int tile = blockIdx.x; tile < TILES_B2; tile += GRID, lt++) {
            int b = lt & 1;
            uint32_t boff = b ? OFF_B1 : OFF_B0;
            int t0 = tile * TOK_B;
            int T = min(TOK_B, TOKENS - t0);
            int rows9 = 9 * T;
            bar_sync(BAR_FULL(b), NTHREADS);

            float acc[2][4][4];
            gemm_tile(sb, OFF_W, boff, lane, r0, n0, acc);
            bar_arrive(BAR_EMPTY(b), NTHREADS);   // buffer free; store from regs

            // direct store: out[(t0+t)*2304 + O*9 + ij]; cols s are consecutive
            #pragma unroll
            for (int mt = 0; mt < 2; mt++)
                #pragma unroll
                for (int h8 = 0; h8 < 2; h8++) {
                    int O = r0 + mt * 16 + h8 * 8 + (lane >> 2);
                    float* ob = out + (size_t)t0 * 2304 + (size_t)O * 9;
                    #pragma unroll
                    for (int nt = 0; nt < 4; nt++) {
                        int s = n0 + nt * 8 + ((lane & 3) << 1);
                        float v0 = acc[mt][nt][h8 * 2], v1 = acc[mt][nt][h8 * 2 + 1];
                        int t1 = s / 9, ij = s - t1 * 9;
                        if (s < rows9)     ob[t1 * 2304 + ij] = v0;
                        if (s + 1 < rows9) {
                            if (ij < 8) ob[t1 * 2304 + ij + 1] = v1;
                            else        ob[(t1 + 1) * 2304]    = v1;
                        }
                    }
                }
        }
    } else {                                  // ---- producers (build only) ----
        const int ptid = tid - CONS_T;
        int lt = 0;
        for (int tile = blockIdx.x; tile < TILES_B2; tile += GRID, lt++) {
            int b = lt & 1;
            uint32_t boff = b ? OFF_B1 : OFF_B0;
            int t0 = tile * TOK_B;
            int T = min(TOK_B, TOKENS - t0);
            int rows = 9 * T;
            if (lt >= 2) bar_sync(BAR_EMPTY(b), NTHREADS);
            for (int c = ptid; c < 3072; c += PROD_T) {  // 96 rows x 32 chunks
                int row = c >> 5, kc = c & 31;
                uint4 o = make_uint4(0, 0, 0, 0);
                if (row < rows) {
                    int tl = row / 9, ij = row - tl * 9;
                    int i = ij / 3, j = ij - i * 3;
                    size_t base = ((size_t)(t0 + tl) * 3) * 256 + kc * 8;
                    uint4 a = *reinterpret_cast<const uint4*>(g_XL + base + (size_t)i * 256);
                    uint4 bb = *reinterpret_cast<const uint4*>(g_XR + base + (size_t)j * 256);
                    o.x = hmul2u(a.x, bb.x); o.y = hmul2u(a.y, bb.y);
                    o.z = hmul2u(a.z, bb.z); o.w = hmul2u(a.w, bb.w);
                }
                *reinterpret_cast<uint4*>(smem + boff + sw(row, kc)) = o;
            }
            bar_arrive(BAR_FULL(b), NTHREADS);
        }
    }
}

extern "C" void kernel_launch(void* const* d_in, const int* in_sizes, int n_in,
                              void* d_out, int out_size) {
    const float* x_l = (const float*)d_in[0];
    const float* x_r = (const float*)d_in[1];
    const float* w_l = (const float*)d_in[2];
    const float* w_r = (const float*)d_in[3];
    const float* w_o = (const float*)d_in[4];
    float* out = (float*)d_out;

    cudaFuncSetAttribute(kA, cudaFuncAttributeMaxDynamicSharedMemorySize, SMEM_BYTES);
    cudaFuncSetAttribute(kB, cudaFuncAttributeMaxDynamicSharedMemorySize, SMEM_BYTES);

    kA<<<2 * GRID, NTHREADS, SMEM_BYTES>>>(x_l, x_r, w_l, w_r);
    kB<<<GRID, NTHREADS, SMEM_BYTES>>>(w_o, out);
}

// round 14
// speedup vs baseline: 1.0547x; 1.0547x over previous
#include <cuda_runtime.h>
#include <cuda_fp16.h>
#include <cstdint>

#define TOKENS   32768
#define NTHREADS 1024
#define CONS_T   768          // 24 consumer warps; 8 producer warps
#define PROD_T   256
#define GRID     152

#define TOK_A    32           // 96 rows exact
#define TILES_A2 1024         // 32768/32
#define TOK_B    10           // 90 rows (+6 pad)
#define TILES_B2 3277         // ceil(32768/10)

#define OFF_W    0            // 256 rows x 512B = 131072
#define BUF_SZ   49152        // 96 rows x 512B
#define OFF_B0   131072
#define OFF_B1   (131072 + BUF_SZ)
#define SMEM_BYTES (131072 + 2 * BUF_SZ)   // 229376 <= 227KB opt-in

#define BAR_FULL(b)  (1 + (b))
#define BAR_EMPTY(b) (3 + (b))

__device__ __half g_XL[(size_t)TOKENS * 3 * 256];
__device__ __half g_XR[(size_t)TOKENS * 3 * 256];

__device__ __forceinline__ uint32_t smem_u32(const void* p) {
    uint32_t a;
    asm("{ .reg .u64 t; cvta.to.shared.u64 t, %1; cvt.u32.u64 %0, t; }" : "=r"(a) : "l"(p));
    return a;
}
__device__ __forceinline__ void bar_sync(int id, int cnt) {
    asm volatile("bar.sync %0, %1;" :: "r"(id), "r"(cnt) : "memory");
}
__device__ __forceinline__ void bar_arrive(int id, int cnt) {
    asm volatile("bar.arrive %0, %1;" :: "r"(id), "r"(cnt) : "memory");
}
// XOR swizzle: row stride 512B, 16B chunk index ^ (row&7)
__device__ __forceinline__ uint32_t sw(uint32_t row, uint32_t kc) {
    return row * 512u + (((kc ^ (row & 7u)) & 31u) << 4);
}
__device__ __forceinline__ void ldsm_x4(uint32_t addr, uint32_t* r) {
    asm volatile("ldmatrix.sync.aligned.m8n8.x4.shared.b16 {%0,%1,%2,%3}, [%4];"
                 : "=r"(r[0]), "=r"(r[1]), "=r"(r[2]), "=r"(r[3]) : "r"(addr));
}
__device__ __forceinline__ void mma16816(float* c, const uint32_t* a, const uint32_t* b) {
    asm volatile("mma.sync.aligned.m16n8k16.row.col.f32.f16.f16.f32 "
                 "{%0,%1,%2,%3}, {%4,%5,%6,%7}, {%8,%9}, {%0,%1,%2,%3};"
                 : "+f"(c[0]), "+f"(c[1]), "+f"(c[2]), "+f"(c[3])
                 : "r"(a[0]), "r"(a[1]), "r"(a[2]), "r"(a[3]), "r"(b[0]), "r"(b[1]));
}
__device__ __forceinline__ uint32_t f2h2(float a, float b) {
    __half2 h = __floats2half2_rn(a, b);
    return *reinterpret_cast<uint32_t*>(&h);
}
__device__ __forceinline__ uint32_t hmul2u(uint32_t a, uint32_t b) {
    __half2 r = __hmul2(*reinterpret_cast<__half2*>(&a), *reinterpret_cast<__half2*>(&b));
    return *reinterpret_cast<uint32_t*>(&r);
}

// Full 256-row fp32 weight -> fp16 swizzled smem (128KB), all 1024 threads
__device__ __forceinline__ void load_w(char* smem, const float* W, int tid) {
    for (int c = tid; c < 8192; c += NTHREADS) {
        int row = c >> 5, kc = c & 31;
        const float* s = W + (size_t)row * 256 + kc * 8;
        float4 f0 = *reinterpret_cast<const float4*>(s);
        float4 f1 = *reinterpret_cast<const float4*>(s + 4);
        uint4 v;
        v.x = f2h2(f0.x, f0.y); v.y = f2h2(f0.z, f0.w);
        v.z = f2h2(f1.x, f1.y); v.w = f2h2(f1.z, f1.w);
        *reinterpret_cast<uint4*>(smem + OFF_W + sw(row, kc)) = v;
    }
}

// GEMM: acc[M rows from a_base @ r0][N cols from b_base @ n0], K=256.
__device__ __forceinline__ void gemm_tile(uint32_t sb, uint32_t a_base, uint32_t b_base,
                                          int lane, int r0, int n0, float acc[2][4][4]) {
    #pragma unroll
    for (int mt = 0; mt < 2; mt++)
        #pragma unroll
        for (int nt = 0; nt < 4; nt++)
            #pragma unroll
            for (int q = 0; q < 4; q++) acc[mt][nt][q] = 0.f;

    const int la_row = (lane & 7) | (((lane >> 3) & 1) << 3);
    const int la_kc  = lane >> 4;
    const int lb_row = (lane & 7) | ((lane >> 4) << 3);
    const int lb_kc  = (lane >> 3) & 1;

    #pragma unroll 4
    for (int kc = 0; kc < 32; kc += 2) {
        uint32_t a[2][4], b[2][4];
        #pragma unroll
        for (int mt = 0; mt < 2; mt++)
            ldsm_x4(sb + a_base + sw(r0 + mt * 16 + la_row, kc + la_kc), a[mt]);
        #pragma unroll
        for (int p = 0; p < 2; p++)
            ldsm_x4(sb + b_base + sw(n0 + p * 16 + lb_row, kc + lb_kc), b[p]);
        #pragma unroll
        for (int mt = 0; mt < 2; mt++)
            #pragma unroll
            for (int nt = 0; nt < 4; nt++)
                mma16816(acc[mt][nt], a[mt], &b[nt >> 1][(nt & 1) * 2]);
    }
}

// ---- kA (merged L/R): XO[(t*3+i), r] = sum_I x[t,I,i] * W[r,I]; 32 tokens/tile ----
__global__ void __launch_bounds__(NTHREADS, 1) kA(const float* __restrict__ x_l,
                                                  const float* __restrict__ x_r,
                                                  const float* __restrict__ w_l,
                                                  const float* __restrict__ w_r) {
    extern __shared__ __align__(128) char smem[];
    uint32_t sb = smem_u32(smem);
    const int tid = threadIdx.x, lane = tid & 31;
    const int side = blockIdx.x >= GRID;
    const int bx = side ? blockIdx.x - GRID : blockIdx.x;
    const float* x = side ? x_r : x_l;
    __half* XO = side ? g_XR : g_XL;

    load_w(smem, side ? w_r : w_l, tid);
    __syncthreads();

    if (tid < CONS_T) {                       // ---- consumers ----
        const int wid = tid >> 5;
        const int r0 = (wid >> 3) * 32, n0 = (wid & 7) * 32;
        int lt = 0;
        for (int tile = bx; tile < TILES_A2; tile += GRID, lt++) {
            int b = lt & 1;
            uint32_t boff = b ? OFF_B1 : OFF_B0;
            bar_sync(BAR_FULL(b), NTHREADS);

            float acc[2][4][4];
            gemm_tile(sb, boff, OFF_W, lane, r0, n0, acc);
            bar_arrive(BAR_EMPTY(b), NTHREADS);   // buffer free; store from regs

            int t0 = tile * TOK_A;
            #pragma unroll
            for (int mt = 0; mt < 2; mt++) {
                int row = r0 + mt * 16 + (lane >> 2);
                __half* d0 = XO + ((size_t)(t0 * 3 + row)) * 256;
                __half* d1 = XO + ((size_t)(t0 * 3 + row + 8)) * 256;
                #pragma unroll
                for (int nt = 0; nt < 4; nt++) {
                    int col = n0 + nt * 8 + (lane & 3) * 2;
                    *reinterpret_cast<uint32_t*>(d0 + col) = f2h2(acc[mt][nt][0], acc[mt][nt][1]);
                    *reinterpret_cast<uint32_t*>(d1 + col) = f2h2(acc[mt][nt][2], acc[mt][nt][3]);
                }
            }
        }
    } else {                                  // ---- producers (build only) ----
        const int ptid = tid - CONS_T;
        int lt = 0;
        for (int tile = bx; tile < TILES_A2; tile += GRID, lt++) {
            int b = lt & 1;
            uint32_t boff = b ? OFF_B1 : OFF_B0;
            if (lt >= 2) bar_sync(BAR_EMPTY(b), NTHREADS);
            const float* src = x + (size_t)(tile * TOK_A) * 768;
            for (int q = ptid; q < 4096; q += PROD_T) {
                int tl = q >> 7, I2 = (q & 127) << 1;
                const float* s = src + tl * 768 + I2 * 3;
                float v0 = s[0], v1 = s[1], v2 = s[2], v3 = s[3], v4 = s[4], v5 = s[5];
                int row = tl * 3;
                uint32_t kc = (uint32_t)I2 >> 3, off = ((uint32_t)I2 & 7u) * 2u;
                *reinterpret_cast<uint32_t*>(smem + boff + sw(row, kc) + off)     = f2h2(v0, v3);
                *reinterpret_cast<uint32_t*>(smem + boff + sw(row + 1, kc) + off) = f2h2(v1, v4);
                *reinterpret_cast<uint32_t*>(smem + boff + sw(row + 2, kc) + off) = f2h2(v2, v5);
            }
            bar_arrive(BAR_FULL(b), NTHREADS);
        }
    }
}

// ---- kB (transposed GEMM + fp16 staged epilogue): D[O, s] = Wo @ P^T ----
__global__ void __launch_bounds__(NTHREADS, 1) kB(const float* __restrict__ Wo,
                                                  float* __restrict__ out) {
    extern __shared__ __align__(128) char smem[];
    uint32_t sb = smem_u32(smem);
    const int tid = threadIdx.x, lane = tid & 31;

    load_w(smem, Wo, tid);
    __syncthreads();

    if (tid < CONS_T) {                       // ---- consumers ----
        const int wid = tid >> 5;
        const int r0 = (wid & 7) * 32;        // O dim: 8 warps x 32
        const int n0 = (wid >> 3) * 32;       // s dim: 3 warps x 32
        // tile-invariant per nt: s -> (tl, ij)
        int s_q[4], t1_q[4], ij_q[4];
        #pragma unroll
        for (int nt = 0; nt < 4; nt++) {
            s_q[nt] = n0 + nt * 8 + ((lane & 3) << 1);
            t1_q[nt] = s_q[nt] / 9;
            ij_q[nt] = s_q[nt] - 9 * t1_q[nt];
        }
        int lt = 0;
        for (int tile = blockIdx.x; tile < TILES_B2; tile += GRID, lt++) {
            int b = lt & 1;
            uint32_t boff = b ? OFF_B1 : OFF_B0;
            int t0 = tile * TOK_B;
            int T = min(TOK_B, TOKENS - t0);
            int rows9 = 9 * T;
            bar_sync(BAR_FULL(b), NTHREADS);

            float acc[2][4][4];
            gemm_tile(sb, OFF_W, boff, lane, r0, n0, acc);
            bar_sync(5, CONS_T);              // all ldsm done before restage

            // single-pass fp16 staging: [tl][O][ij] (4608B/token, 18B/O-row)
            #pragma unroll
            for (int mt = 0; mt < 2; mt++)
                #pragma unroll
                for (int h8 = 0; h8 < 2; h8++) {
                    uint32_t obase = boff + (uint32_t)(r0 + mt * 16 + h8 * 8 + (lane >> 2)) * 18u;
                    #pragma unroll
                    for (int nt = 0; nt < 4; nt++) {
                        int s = s_q[nt];
                        if (s < rows9) {
                            uint32_t a0 = obase + (uint32_t)t1_q[nt] * 4608u
                                        + (uint32_t)ij_q[nt] * 2u;
                            *reinterpret_cast<__half*>(smem + a0) =
                                __float2half_rn(acc[mt][nt][h8 * 2]);
                            if (s + 1 < rows9) {
                                uint32_t a1 = (ij_q[nt] == 8)
                                    ? obase + (uint32_t)(t1_q[nt] + 1) * 4608u
                                    : a0 + 2u;
                                *reinterpret_cast<__half*>(smem + a1) =
                                    __float2half_rn(acc[mt][nt][h8 * 2 + 1]);
                            }
                        }
                    }
                }
            bar_sync(5, CONS_T);

            // linear copy-out: uint4 (8 fp16) -> 8 fp32; layout matches out exactly
            int nvec = T * 288;
            for (int e = tid; e < nvec; e += CONS_T) {
                uint4 v = *reinterpret_cast<const uint4*>(smem + boff + e * 16);
                int tl = e / 288, r4 = e - tl * 288;
                float* dst = out + (size_t)(t0 + tl) * 2304 + r4 * 8;
                float2 f0 = __half22float2(*reinterpret_cast<__half2*>(&v.x));
                float2 f1 = __half22float2(*reinterpret_cast<__half2*>(&v.y));
                float2 f2 = __half22float2(*reinterpret_cast<__half2*>(&v.z));
                float2 f3 = __half22float2(*reinterpret_cast<__half2*>(&v.w));
                *reinterpret_cast<float4*>(dst)     = make_float4(f0.x, f0.y, f1.x, f1.y);
                *reinterpret_cast<float4*>(dst + 4) = make_float4(f2.x, f2.y, f3.x, f3.y);
            }
            bar_arrive(BAR_EMPTY(b), NTHREADS);
        }
    } else {                                  // ---- producers (build only) ----
        const int ptid = tid - CONS_T;
        int lt = 0;
        for (int tile = blockIdx.x; tile < TILES_B2; tile += GRID, lt++) {
            int b = lt & 1;
            uint32_t boff = b ? OFF_B1 : OFF_B0;
            int t0 = tile * TOK_B;
            int T = min(TOK_B, TOKENS - t0);
            int rows = 9 * T;
            if (lt >= 2) bar_sync(BAR_EMPTY(b), NTHREADS);
            for (int c = ptid; c < 3072; c += PROD_T) {  // 96 rows x 32 chunks
                int row = c >> 5, kc = c & 31;
                uint4 o = make_uint4(0, 0, 0, 0);
                if (row < rows) {
                    int tl = row / 9, ij = row - tl * 9;
                    int i = ij / 3, j = ij - i * 3;
                    size_t base = ((size_t)(t0 + tl) * 3) * 256 + kc * 8;
                    uint4 a = *reinterpret_cast<const uint4*>(g_XL + base + (size_t)i * 256);
                    uint4 bb = *reinterpret_cast<const uint4*>(g_XR + base + (size_t)j * 256);
                    o.x = hmul2u(a.x, bb.x); o.y = hmul2u(a.y, bb.y);
                    o.z = hmul2u(a.z, bb.z); o.w = hmul2u(a.w, bb.w);
                }
                *reinterpret_cast<uint4*>(smem + boff + sw(row, kc)) = o;
            }
            bar_arrive(BAR_FULL(b), NTHREADS);
        }
    }
}

extern "C" void kernel_launch(void* const* d_in, const int* in_sizes, int n_in,
                              void* d_out, int out_size) {
    const float* x_l = (const float*)d_in[0];
    const float* x_r = (const float*)d_in[1];
    const float* w_l = (const float*)d_in[2];
    const float* w_r = (const float*)d_in[3];
    const float* w_o = (const float*)d_in[4];
    float* out = (float*)d_out;

    cudaFuncSetAttribute(kA, cudaFuncAttributeMaxDynamicSharedMemorySize, SMEM_BYTES);
    cudaFuncSetAttribute(kB, cudaFuncAttributeMaxDynamicSharedMemorySize, SMEM_BYTES);

    kA<<<2 * GRID, NTHREADS, SMEM_BYTES>>>(x_l, x_r, w_l, w_r);
    kB<<<GRID, NTHREADS, SMEM_BYTES>>>(w_o, out);
}

// round 15
// speedup vs baseline: 1.1297x; 1.0711x over previous
#include <cuda_runtime.h>
#include <cuda_fp16.h>
#include <cstdint>

#define TOKENS   32768
#define NTHREADS 1024
#define CONS_T   768          // 24 consumer warps; 8 producer warps
#define PROD_T   256
#define GRID     152

#define TOK_A    32           // 96 rows exact
#define TILES_A2 1024         // 32768/32
#define TOK_B    10           // 90 rows (+6 pad)
#define TILES_B2 3277         // ceil(32768/10)

#define OFF_W    0            // 256 rows x 512B = 131072
#define BUF_SZ   49152        // 96 rows x 512B
#define OFF_B0   131072
#define OFF_B1   (131072 + BUF_SZ)
#define SMEM_BYTES (131072 + 2 * BUF_SZ)   // 229376 <= 227KB opt-in

#define BAR_FULL(b)  (1 + (b))
#define BAR_EMPTY(b) (3 + (b))

__device__ __half g_XL[(size_t)TOKENS * 3 * 256];
__device__ __half g_XR[(size_t)TOKENS * 3 * 256];

__device__ __forceinline__ uint32_t smem_u32(const void* p) {
    uint32_t a;
    asm("{ .reg .u64 t; cvta.to.shared.u64 t, %1; cvt.u32.u64 %0, t; }" : "=r"(a) : "l"(p));
    return a;
}
__device__ __forceinline__ void bar_sync(int id, int cnt) {
    asm volatile("bar.sync %0, %1;" :: "r"(id), "r"(cnt) : "memory");
}
__device__ __forceinline__ void bar_arrive(int id, int cnt) {
    asm volatile("bar.arrive %0, %1;" :: "r"(id), "r"(cnt) : "memory");
}
// XOR swizzle: row stride 512B, 16B chunk index ^ (row&7)
__device__ __forceinline__ uint32_t sw(uint32_t row, uint32_t kc) {
    return row * 512u + (((kc ^ (row & 7u)) & 31u) << 4);
}
__device__ __forceinline__ void ldsm_x4(uint32_t addr, uint32_t* r) {
    asm volatile("ldmatrix.sync.aligned.m8n8.x4.shared.b16 {%0,%1,%2,%3}, [%4];"
                 : "=r"(r[0]), "=r"(r[1]), "=r"(r[2]), "=r"(r[3]) : "r"(addr));
}
__device__ __forceinline__ void mma16816(float* c, const uint32_t* a, const uint32_t* b) {
    asm volatile("mma.sync.aligned.m16n8k16.row.col.f32.f16.f16.f32 "
                 "{%0,%1,%2,%3}, {%4,%5,%6,%7}, {%8,%9}, {%0,%1,%2,%3};"
                 : "+f"(c[0]), "+f"(c[1]), "+f"(c[2]), "+f"(c[3])
                 : "r"(a[0]), "r"(a[1]), "r"(a[2]), "r"(a[3]), "r"(b[0]), "r"(b[1]));
}
__device__ __forceinline__ uint32_t f2h2(float a, float b) {
    __half2 h = __floats2half2_rn(a, b);
    return *reinterpret_cast<uint32_t*>(&h);
}
__device__ __forceinline__ uint32_t hmul2u(uint32_t a, uint32_t b) {
    __half2 r = __hmul2(*reinterpret_cast<__half2*>(&a), *reinterpret_cast<__half2*>(&b));
    return *reinterpret_cast<uint32_t*>(&r);
}

// Full 256-row fp32 weight -> fp16 swizzled smem (128KB), all 1024 threads
__device__ __forceinline__ void load_w(char* smem, const float* W, int tid) {
    for (int c = tid; c < 8192; c += NTHREADS) {
        int row = c >> 5, kc = c & 31;
        const float* s = W + (size_t)row * 256 + kc * 8;
        float4 f0 = *reinterpret_cast<const float4*>(s);
        float4 f1 = *reinterpret_cast<const float4*>(s + 4);
        uint4 v;
        v.x = f2h2(f0.x, f0.y); v.y = f2h2(f0.z, f0.w);
        v.z = f2h2(f1.x, f1.y); v.w = f2h2(f1.z, f1.w);
        *reinterpret_cast<uint4*>(smem + OFF_W + sw(row, kc)) = v;
    }
}

// GEMM: acc[M rows from a_base @ r0][N cols from b_base @ n0], K=256.
__device__ __forceinline__ void gemm_tile(uint32_t sb, uint32_t a_base, uint32_t b_base,
                                          int lane, int r0, int n0, float acc[2][4][4]) {
    #pragma unroll
    for (int mt = 0; mt < 2; mt++)
        #pragma unroll
        for (int nt = 0; nt < 4; nt++)
            #pragma unroll
            for (int q = 0; q < 4; q++) acc[mt][nt][q] = 0.f;

    const int la_row = (lane & 7) | (((lane >> 3) & 1) << 3);
    const int la_kc  = lane >> 4;
    const int lb_row = (lane & 7) | ((lane >> 4) << 3);
    const int lb_kc  = (lane >> 3) & 1;

    #pragma unroll 4
    for (int kc = 0; kc < 32; kc += 2) {
        uint32_t a[2][4], b[2][4];
        #pragma unroll
        for (int mt = 0; mt < 2; mt++)
            ldsm_x4(sb + a_base + sw(r0 + mt * 16 + la_row, kc + la_kc), a[mt]);
        #pragma unroll
        for (int p = 0; p < 2; p++)
            ldsm_x4(sb + b_base + sw(n0 + p * 16 + lb_row, kc + lb_kc), b[p]);
        #pragma unroll
        for (int mt = 0; mt < 2; mt++)
            #pragma unroll
            for (int nt = 0; nt < 4; nt++)
                mma16816(acc[mt][nt], a[mt], &b[nt >> 1][(nt & 1) * 2]);
    }
}

// ---- kA (merged L/R): XO[(t*3+i), r] = sum_I x[t,I,i] * W[r,I]; 32 tokens/tile ----
// Consumers direct-store fp16 from registers (coalesced pairs); producers build.
__global__ void __launch_bounds__(NTHREADS, 1) kA(const float* __restrict__ x_l,
                                                  const float* __restrict__ x_r,
                                                  const float* __restrict__ w_l,
                                                  const float* __restrict__ w_r) {
    extern __shared__ __align__(128) char smem[];
    uint32_t sb = smem_u32(smem);
    const int tid = threadIdx.x, lane = tid & 31;
    const int side = blockIdx.x >= GRID;
    const int bx = side ? blockIdx.x - GRID : blockIdx.x;
    const float* x = side ? x_r : x_l;
    __half* XO = side ? g_XR : g_XL;

    load_w(smem, side ? w_r : w_l, tid);
    __syncthreads();

    if (tid < CONS_T) {                       // ---- consumers ----
        const int wid = tid >> 5;
        const int r0 = (wid >> 3) * 32, n0 = (wid & 7) * 32;
        int lt = 0;
        for (int tile = bx; tile < TILES_A2; tile += GRID, lt++) {
            int b = lt & 1;
            uint32_t boff = b ? OFF_B1 : OFF_B0;
            bar_sync(BAR_FULL(b), NTHREADS);

            float acc[2][4][4];
            gemm_tile(sb, boff, OFF_W, lane, r0, n0, acc);
            bar_arrive(BAR_EMPTY(b), NTHREADS);   // buffer free; store from regs

            int t0 = tile * TOK_A;
            #pragma unroll
            for (int mt = 0; mt < 2; mt++) {
                int row = r0 + mt * 16 + (lane >> 2);
                __half* d0 = XO + ((size_t)(t0 * 3 + row)) * 256;
                __half* d1 = XO + ((size_t)(t0 * 3 + row + 8)) * 256;
                #pragma unroll
                for (int nt = 0; nt < 4; nt++) {
                    int col = n0 + nt * 8 + (lane & 3) * 2;
                    *reinterpret_cast<uint32_t*>(d0 + col) = f2h2(acc[mt][nt][0], acc[mt][nt][1]);
                    *reinterpret_cast<uint32_t*>(d1 + col) = f2h2(acc[mt][nt][2], acc[mt][nt][3]);
                }
            }
        }
    } else {                                  // ---- producers (build only) ----
        const int ptid = tid - CONS_T;
        int lt = 0;
        for (int tile = bx; tile < TILES_A2; tile += GRID, lt++) {
            int b = lt & 1;
            uint32_t boff = b ? OFF_B1 : OFF_B0;
            if (lt >= 2) bar_sync(BAR_EMPTY(b), NTHREADS);
            const float* src = x + (size_t)(tile * TOK_A) * 768;
            for (int q = ptid; q < 4096; q += PROD_T) {
                int tl = q >> 7, I2 = (q & 127) << 1;
                const float* s = src + tl * 768 + I2 * 3;
                float v0 = s[0], v1 = s[1], v2 = s[2], v3 = s[3], v4 = s[4], v5 = s[5];
                int row = tl * 3;
                uint32_t kc = (uint32_t)I2 >> 3, off = ((uint32_t)I2 & 7u) * 2u;
                *reinterpret_cast<uint32_t*>(smem + boff + sw(row, kc) + off)     = f2h2(v0, v3);
                *reinterpret_cast<uint32_t*>(smem + boff + sw(row + 1, kc) + off) = f2h2(v1, v4);
                *reinterpret_cast<uint32_t*>(smem + boff + sw(row + 2, kc) + off) = f2h2(v2, v5);
            }
            bar_arrive(BAR_FULL(b), NTHREADS);
        }
    }
}

// ---- kB (R10 epilogue): out[t,O,ij] = sum_r Wo[O,r]*XL[t,i,r]*XR[t,j,r] ----
// Stage fp32 TRANSPOSED [tl][O][ij], two 128-col half passes, linear copy-out.
__global__ void __launch_bounds__(NTHREADS, 1) kB(const float* __restrict__ Wo,
                                                  float* __restrict__ out) {
    extern __shared__ __align__(128) char smem[];
    uint32_t sb = smem_u32(smem);
    const int tid = threadIdx.x, lane = tid & 31;

    load_w(smem, Wo, tid);
    __syncthreads();

    if (tid < CONS_T) {                       // ---- consumers ----
        const int wid = tid >> 5;
        const int r0 = (wid >> 3) * 32, n0 = (wid & 7) * 32;
        const int hh_own = n0 >> 7;
        const int cb = n0 & 127;
        // tile-invariant: staged row -> (tl, ij) for the 4 acc row groups
        int tl_q[4], ij_q[4];
        #pragma unroll
        for (int q = 0; q < 4; q++) {
            int row = r0 + q * 8 + (lane >> 2);
            tl_q[q] = row / 9;
            ij_q[q] = row - 9 * tl_q[q];
        }
        int lt = 0;
        for (int tile = blockIdx.x; tile < TILES_B2; tile += GRID, lt++) {
            int b = lt & 1;
            uint32_t boff = b ? OFF_B1 : OFF_B0;
            int t0 = tile * TOK_B;
            int T = min(TOK_B, TOKENS - t0);
            bar_sync(BAR_FULL(b), NTHREADS);

            float acc[2][4][4];
            gemm_tile(sb, boff, OFF_W, lane, r0, n0, acc);
            bar_sync(5, CONS_T);

            // two 128-col half passes; stage TRANSPOSED [tl][O][ij] (4608B per tl)
            #pragma unroll
            for (int hh = 0; hh < 2; hh++) {
                if (hh_own == hh) {
                    #pragma unroll
                    for (int mt = 0; mt < 2; mt++)
                        #pragma unroll
                        for (int h8 = 0; h8 < 2; h8++) {
                            int q = mt * 2 + h8;
                            if (tl_q[q] < T) {
                                uint32_t base = boff + (uint32_t)tl_q[q] * 4608u
                                              + (uint32_t)ij_q[q] * 4u;
                                #pragma unroll
                                for (int nt = 0; nt < 4; nt++) {
                                    int col = cb + nt * 8 + (lane & 3) * 2;
                                    *reinterpret_cast<float*>(smem + base + col * 36) =
                                        acc[mt][nt][h8 * 2];
                                    *reinterpret_cast<float*>(smem + base + (col + 1) * 36) =
                                        acc[mt][nt][h8 * 2 + 1];
                                }
                            }
                        }
                }
                bar_sync(5, CONS_T);
                // linear vectorized copy-out: 288 uint4 per token per half
                int nvec = T * 288;
                for (int e = tid; e < nvec; e += CONS_T) {
                    int tl = e / 288, r4 = e - tl * 288;
                    uint4 v = *reinterpret_cast<const uint4*>(smem + boff + e * 16);
                    *reinterpret_cast<uint4*>(out + (size_t)(t0 + tl) * 2304
                                              + hh * 1152 + r4 * 4) = v;
                }
                bar_sync(5, CONS_T);
            }
            bar_arrive(BAR_EMPTY(b), NTHREADS);
        }
    } else {                                  // ---- producers (build only) ----
        const int ptid = tid - CONS_T;
        int lt = 0;
        for (int tile = blockIdx.x; tile < TILES_B2; tile += GRID, lt++) {
            int b = lt & 1;
            uint32_t boff = b ? OFF_B1 : OFF_B0;
            int t0 = tile * TOK_B;
            int T = min(TOK_B, TOKENS - t0);
            int rows = 9 * T;
            if (lt >= 2) bar_sync(BAR_EMPTY(b), NTHREADS);
            for (int c = ptid; c < 3072; c += PROD_T) {  // 96 rows x 32 chunks
                int row = c >> 5, kc = c & 31;
                uint4 o = make_uint4(0, 0, 0, 0);
                if (row < rows) {
                    int tl = row / 9, ij = row - tl * 9;
                    int i = ij / 3, j = ij - i * 3;
                    size_t base = ((size_t)(t0 + tl) * 3) * 256 + kc * 8;
                    uint4 a = *reinterpret_cast<const uint4*>(g_XL + base + (size_t)i * 256);
                    uint4 bb = *reinterpret_cast<const uint4*>(g_XR + base + (size_t)j * 256);
                    o.x = hmul2u(a.x, bb.x); o.y = hmul2u(a.y, bb.y);
                    o.z = hmul2u(a.z, bb.z); o.w = hmul2u(a.w, bb.w);
                }
                *reinterpret_cast<uint4*>(smem + boff + sw(row, kc)) = o;
            }
            bar_arrive(BAR_FULL(b), NTHREADS);
        }
    }
}

extern "C" void kernel_launch(void* const* d_in, const int* in_sizes, int n_in,
                              void* d_out, int out_size) {
    const float* x_l = (const float*)d_in[0];
    const float* x_r = (const float*)d_in[1];
    const float* w_l = (const float*)d_in[2];
    const float* w_r = (const float*)d_in[3];
    const float* w_o = (const float*)d_in[4];
    float* out = (float*)d_out;

    cudaFuncSetAttribute(kA, cudaFuncAttributeMaxDynamicSharedMemorySize, SMEM_BYTES);
    cudaFuncSetAttribute(kB, cudaFuncAttributeMaxDynamicSharedMemorySize, SMEM_BYTES);

    kA<<<2 * GRID, NTHREADS, SMEM_BYTES>>>(x_l, x_r, w_l, w_r);
    kB<<<GRID, NTHREADS, SMEM_BYTES>>>(w_o, out);
}